// round 7
// baseline (speedup 1.0000x reference)
#include <cuda_runtime.h>
#include <math.h>

// Problem constants
#define B_TOT  16384
#define T_LEN  128
#define F_DIM  9
#define H_DIM  128
#define O_DIM  12
#define G_DIM  512     // 4*H
#define TILE_B 64
#define NTH    512     // 16 warps: warp owns 4 rows, lane owns 4 units
#define KC     16      // k-chunk staged per ping-pong step

typedef unsigned long long ull;

// ---------------- packed f32x2 helpers ----------------
__device__ __forceinline__ ull pk2(float x, float y) {
    ull r;
    asm("mov.b64 %0, {%1, %2};" : "=l"(r) : "f"(x), "f"(y));
    return r;
}
__device__ __forceinline__ void unpk2(ull v, float& lo, float& hi) {
    asm("mov.b64 {%0, %1}, %2;" : "=f"(lo), "=f"(hi) : "l"(v));
}
__device__ __forceinline__ ull fma2(ull a, ull b, ull c) {
    ull d;
    asm("fma.rn.f32x2 %0, %1, %2, %3;" : "=l"(d) : "l"(a), "l"(b), "l"(c));
    return d;
}

// ---------------- pointwise gate math ----------------
__device__ __forceinline__ float sigf(float x) {
    return __fdividef(1.0f, 1.0f + __expf(-x));
}
__device__ __forceinline__ float tanhfast(float x) {
    float xc = fminf(fmaxf(x, -15.0f), 15.0f);
    float e = __expf(2.0f * xc);
    return __fdividef(e - 1.0f, e + 1.0f);
}

// ---------------- precomputed folded weights ----------------
// WeffT = (Wih0 @ W_in) stored transposed [9][512]
// beff = Wih0 @ b_in + bih0 + bhh0 ; bias1 = bih1 + bhh1
__device__ float g_WeffT[F_DIM * G_DIM];
__device__ float g_beff[G_DIM];
__device__ float g_bias1[G_DIM];

__global__ void precompute_kernel(const float* __restrict__ Wih0,
                                  const float* __restrict__ W_in,
                                  const float* __restrict__ b_in,
                                  const float* __restrict__ bih0,
                                  const float* __restrict__ bhh0,
                                  const float* __restrict__ bih1,
                                  const float* __restrict__ bhh1) {
    int j = threadIdx.x;  // 0..511
    float acc[F_DIM];
#pragma unroll
    for (int f = 0; f < F_DIM; f++) acc[f] = 0.0f;
    float bacc = 0.0f;
    for (int k = 0; k < H_DIM; k++) {
        float w = Wih0[j * H_DIM + k];
        bacc += w * b_in[k];
#pragma unroll
        for (int f = 0; f < F_DIM; f++) acc[f] += w * W_in[k * F_DIM + f];
    }
#pragma unroll
    for (int f = 0; f < F_DIM; f++) g_WeffT[f * G_DIM + j] = acc[f];
    g_beff[j] = bacc + bih0[j] + bhh0[j];
    g_bias1[j] = bih1[j] + bhh1[j];
}

// ---------------- helpers for the main kernel ----------------
__device__ __forceinline__ void init_acc(const float* __restrict__ sBias, int u0,
                                         ull (&acc)[4][2][4]) {
#pragma unroll
    for (int g = 0; g < 4; g++) {
#pragma unroll
        for (int up = 0; up < 2; up++) {
            ull b = *(const ull*)(sBias + g * H_DIM + u0 + 2 * up);
#pragma unroll
            for (int r = 0; r < 4; r++) acc[g][up][r] = b;
        }
    }
}

// prefetch one KC=16 chunk of one weight matrix: thread owns column j
__device__ __forceinline__ void ldg_chunk(int m,
                                          const float* __restrict__ Whh0,
                                          const float* __restrict__ Wih1,
                                          const float* __restrict__ Whh1,
                                          int j, float4 (&ra)[4]) {
    const float* src = (m < 8) ? Whh0 : ((m < 16) ? Wih1 : Whh1);
    const float4* p = (const float4*)(src + (size_t)j * H_DIM + (m & 7) * KC);
#pragma unroll
    for (int i = 0; i < 4; i++) ra[i] = p[i];
}

// store chunk transposed into staging buffer: buf[k*512 + j]
__device__ __forceinline__ void sts_chunk(float* __restrict__ buf, int j,
                                          const float4 (&ra)[4]) {
#pragma unroll
    for (int i = 0; i < 4; i++) {
        buf[(i * 4 + 0) * G_DIM + j] = ra[i].x;
        buf[(i * 4 + 1) * G_DIM + j] = ra[i].y;
        buf[(i * 4 + 2) * G_DIM + j] = ra[i].z;
        buf[(i * 4 + 3) * G_DIM + j] = ra[i].w;
    }
}

// Inner GEMM over a KC=16 chunk. Sp points to S[r0][k0] (row stride 128).
// h reads vectorized via LDS.128; weight reads LDS.128 from staging buffer.
__device__ __forceinline__ void gemm16(const float* __restrict__ Sp,
                                       const float* __restrict__ buf,
                                       int u0, ull (&acc)[4][2][4]) {
#pragma unroll
    for (int grp = 0; grp < 4; grp++) {
        float4 h4[4];
#pragma unroll
        for (int r = 0; r < 4; r++)
            h4[r] = *(const float4*)(Sp + r * H_DIM + grp * 4);
#pragma unroll
        for (int kk = 0; kk < 4; kk++) {
            int k = grp * 4 + kk;
            ull hp[4];
#pragma unroll
            for (int r = 0; r < 4; r++) {
                float hv = (kk == 0) ? h4[r].x : (kk == 1) ? h4[r].y
                         : (kk == 2) ? h4[r].z : h4[r].w;
                hp[r] = pk2(hv, hv);
            }
#pragma unroll
            for (int g = 0; g < 4; g++) {
                float4 w4 = *(const float4*)(buf + k * G_DIM + g * H_DIM + u0);
                ull w01 = pk2(w4.x, w4.y);
                ull w23 = pk2(w4.z, w4.w);
#pragma unroll
                for (int r = 0; r < 4; r++) {
                    acc[g][0][r] = fma2(w01, hp[r], acc[g][0][r]);
                    acc[g][1][r] = fma2(w23, hp[r], acc[g][1][r]);
                }
            }
        }
    }
}

// x-part GEMM: K=9, weights straight from global (L1/L2 resident, 18KB)
__device__ __forceinline__ void gemm_x(const float* __restrict__ Sp,
                                       int u0, ull (&acc)[4][2][4]) {
#pragma unroll
    for (int k = 0; k < F_DIM; k++) {
        ull hp[4];
#pragma unroll
        for (int r = 0; r < 4; r++) {
            float hv = Sp[r * 12 + k];
            hp[r] = pk2(hv, hv);
        }
#pragma unroll
        for (int g = 0; g < 4; g++) {
            float4 w4 = *(const float4*)(g_WeffT + k * G_DIM + g * H_DIM + u0);
            ull w01 = pk2(w4.x, w4.y);
            ull w23 = pk2(w4.z, w4.w);
#pragma unroll
            for (int r = 0; r < 4; r++) {
                acc[g][0][r] = fma2(w01, hp[r], acc[g][0][r]);
                acc[g][1][r] = fma2(w23, hp[r], acc[g][1][r]);
            }
        }
    }
}

__device__ __forceinline__ void cell_update(ull (&acc)[4][2][4],
                                            float* __restrict__ sC,
                                            float* __restrict__ sH,
                                            int r0, int u0) {
#pragma unroll
    for (int r = 0; r < 4; r++) {
        float vi[4], vf[4], vg[4], vo[4];
        unpk2(acc[0][0][r], vi[0], vi[1]); unpk2(acc[0][1][r], vi[2], vi[3]);
        unpk2(acc[1][0][r], vf[0], vf[1]); unpk2(acc[1][1][r], vf[2], vf[3]);
        unpk2(acc[2][0][r], vg[0], vg[1]); unpk2(acc[2][1][r], vg[2], vg[3]);
        unpk2(acc[3][0][r], vo[0], vo[1]); unpk2(acc[3][1][r], vo[2], vo[3]);
        float* cp = sC + (r0 + r) * H_DIM + u0;
        float4 c4 = *(float4*)cp;
        float co[4] = {c4.x, c4.y, c4.z, c4.w};
        float cn[4], hn[4];
#pragma unroll
        for (int u = 0; u < 4; u++) {
            float gi = sigf(vi[u]);
            float gf = sigf(vf[u]);
            float gg = tanhfast(vg[u]);
            float go = sigf(vo[u]);
            float c_new = gf * co[u] + gi * gg;
            cn[u] = c_new;
            hn[u] = go * tanhfast(c_new);
        }
        *(float4*)cp = make_float4(cn[0], cn[1], cn[2], cn[3]);
        *(float4*)(sH + (r0 + r) * H_DIM + u0) = make_float4(hn[0], hn[1], hn[2], hn[3]);
    }
}

// ---------------- main persistent-tile LSTM kernel ----------------
// grid = 256 CTAs x 512 threads; each CTA owns 64 batch rows for all 128 steps.
// Warp owns 4 rows; lane owns 4 units x 4 gates. acc = 32 ull = 64 regs.
// Weight staging: ping-pong double buffer, ONE barrier per chunk.
__global__ void __launch_bounds__(NTH, 1)
lstm_main(const float* __restrict__ x,
          const float* __restrict__ Whh0,
          const float* __restrict__ Wih1,
          const float* __restrict__ Whh1,
          const float* __restrict__ W_out,
          const float* __restrict__ b_out,
          float* __restrict__ out) {
    extern __shared__ float smem[];
    float* sXs    = smem;                  // 64*12  = 768
    float* sH0    = sXs + 768;             // 8192
    float* sH1    = sH0 + 8192;            // 8192
    float* sC0    = sH1 + 8192;            // 8192
    float* sC1    = sC0 + 8192;            // 8192
    float* sW     = sC1 + 8192;            // 2 x 8192 ping-pong
    float* sBeff  = sW + 16384;            // 512
    float* sBias1 = sBeff + 512;           // 512

    const int tid  = threadIdx.x;
    const int lane = tid & 31;
    const int warp = tid >> 5;
    const int u0 = lane * 4;      // 4 units per thread
    const int r0 = warp * 4;      // 4 rows per warp
    const int b0 = blockIdx.x * TILE_B;

    // init states + resident biases
    for (int i = tid; i < 4 * 8192; i += NTH) sH0[i] = 0.0f;   // H0,H1,C0,C1 contiguous
    for (int i = tid; i < G_DIM; i += NTH) { sBeff[i] = g_beff[i]; sBias1[i] = g_bias1[i]; }
    __syncthreads();

    float4 ra[4];
    ldg_chunk(0, Whh0, Wih1, Whh1, tid, ra);   // prefetch chunk 0

    for (int t = 0; t < T_LEN; t++) {
        // x tile for this timestep
        for (int i = tid; i < TILE_B * F_DIM; i += NTH) {
            int r = i / F_DIM, f = i - r * F_DIM;
            sXs[r * 12 + f] = x[(size_t)(b0 + r) * (T_LEN * F_DIM) + t * F_DIM + f];
        }
        __syncthreads();

        // ---- layer 0 ----
        ull acc[4][2][4];
        init_acc(sBeff, u0, acc);
        gemm_x(&sXs[r0 * 12], u0, acc);                 // folded x-part, K=9
#pragma unroll 1
        for (int m = 0; m < 8; m++) {                   // Whh0, K=128
            float* buf = sW + (m & 1) * 8192;
            sts_chunk(buf, tid, ra);
            ldg_chunk(m + 1, Whh0, Wih1, Whh1, tid, ra);
            __syncthreads();
            gemm16(&sH0[r0 * H_DIM + m * KC], buf, u0, acc);
        }
        __syncthreads();
        cell_update(acc, sC0, sH0, r0, u0);
        __syncthreads();

        // ---- layer 1 ----
        init_acc(sBias1, u0, acc);
#pragma unroll 1
        for (int m = 8; m < 24; m++) {                  // Wih1 (h0-new) then Whh1 (h1-old)
            float* buf = sW + (m & 1) * 8192;
            sts_chunk(buf, tid, ra);
            int mn = (m + 1 == 24) ? 0 : (m + 1);
            ldg_chunk(mn, Whh0, Wih1, Whh1, tid, ra);
            __syncthreads();
            const float* S = (m < 16) ? sH0 : sH1;
            gemm16(&S[r0 * H_DIM + (m & 7) * KC], buf, u0, acc);
        }
        __syncthreads();
        cell_update(acc, sC1, sH1, r0, u0);
        __syncthreads();
    }

    // ---- epilogue: logits + softmax on last h1 ----
    if (tid < TILE_B) {
        int r = tid;
        const float* hr = &sH1[r * H_DIM];
        float lg[O_DIM];
#pragma unroll
        for (int o = 0; o < O_DIM; o++) {
            float s = b_out[o];
            for (int k = 0; k < H_DIM; k++) s += hr[k] * W_out[o * H_DIM + k];
            lg[o] = s;
        }
        float m = lg[0];
#pragma unroll
        for (int o = 1; o < O_DIM; o++) m = fmaxf(m, lg[o]);
        float sum = 0.0f;
#pragma unroll
        for (int o = 0; o < O_DIM; o++) { lg[o] = __expf(lg[o] - m); sum += lg[o]; }
        float inv = __fdividef(1.0f, sum);
#pragma unroll
        for (int o = 0; o < O_DIM; o++) out[(size_t)(b0 + r) * O_DIM + o] = lg[o] * inv;
    }
}

// ---------------- launch ----------------
extern "C" void kernel_launch(void* const* d_in, const int* in_sizes, int n_in,
                              void* d_out, int out_size) {
    (void)in_sizes; (void)n_in; (void)out_size;
    const float* x     = (const float*)d_in[0];
    const float* W_in  = (const float*)d_in[1];
    const float* b_in  = (const float*)d_in[2];
    const float* Wih0  = (const float*)d_in[3];
    const float* Whh0  = (const float*)d_in[4];
    const float* bih0  = (const float*)d_in[5];
    const float* bhh0  = (const float*)d_in[6];
    const float* Wih1  = (const float*)d_in[7];
    const float* Whh1  = (const float*)d_in[8];
    const float* bih1  = (const float*)d_in[9];
    const float* bhh1  = (const float*)d_in[10];
    const float* W_out = (const float*)d_in[11];
    const float* b_out = (const float*)d_in[12];
    float* out = (float*)d_out;

    const size_t smem_bytes = (size_t)(768 + 8192 * 6 + 1024) * sizeof(float); // 203776
    cudaFuncSetAttribute(lstm_main, cudaFuncAttributeMaxDynamicSharedMemorySize, (int)smem_bytes);

    precompute_kernel<<<1, G_DIM>>>(Wih0, W_in, b_in, bih0, bhh0, bih1, bhh1);
    lstm_main<<<B_TOT / TILE_B, NTH, smem_bytes>>>(x, Whh0, Wih1, Whh1, W_out, b_out, out);
}

// round 8
// speedup vs baseline: 1.0107x; 1.0107x over previous
#include <cuda_runtime.h>
#include <math.h>

// Problem constants
#define B_TOT  16384
#define T_LEN  128
#define F_DIM  9
#define H_DIM  128
#define O_DIM  12
#define G_DIM  512     // 4*H
#define TILE_B 64
#define NTH    512     // 16 warps: warp owns 8 rows x 256 cols (2 units x 4 gates per lane)
#define KC     16      // k-chunk staged per ping-pong step

typedef unsigned long long ull;

// ---------------- packed f32x2 helpers ----------------
__device__ __forceinline__ ull pk2(float x, float y) {
    ull r;
    asm("mov.b64 %0, {%1, %2};" : "=l"(r) : "f"(x), "f"(y));
    return r;
}
__device__ __forceinline__ void unpk2(ull v, float& lo, float& hi) {
    asm("mov.b64 {%0, %1}, %2;" : "=f"(lo), "=f"(hi) : "l"(v));
}
__device__ __forceinline__ ull fma2(ull a, ull b, ull c) {
    ull d;
    asm("fma.rn.f32x2 %0, %1, %2, %3;" : "=l"(d) : "l"(a), "l"(b), "l"(c));
    return d;
}

// ---------------- pointwise gate math ----------------
__device__ __forceinline__ float sigf(float x) {
    return __fdividef(1.0f, 1.0f + __expf(-x));
}
__device__ __forceinline__ float tanhfast(float x) {
    float xc = fminf(fmaxf(x, -15.0f), 15.0f);
    float e = __expf(2.0f * xc);
    return __fdividef(e - 1.0f, e + 1.0f);
}

// ---------------- staging permutation ----------------
// Column c (0..511) of a gate matrix decomposes as: g = c>>7 (gate), hf = (c>>6)&1,
// l = (c>>1)&31 (lane), u = c&1. Staged position within a 512-float k-row:
//   pos = (g>>1)*256 + hf*128 + l*4 + (g&1)*2 + u
// Reader (warp-half hf, lane l) then finds its 8 weights per k as TWO contiguous
// float4s at offsets  sel*256 + hf*128 + l*4 , sel = 0/1  -> LDS.128 as ulonglong2,
// each ull already the packed f32x2 (unit u0, u0+1) for one gate.
__device__ __forceinline__ int stage_pos(int c) {
    int g = c >> 7, hf = (c >> 6) & 1, l = (c >> 1) & 31, u = c & 1;
    return ((g >> 1) << 8) + (hf << 7) + (l << 2) + ((g & 1) << 1) + u;
}

// ---------------- precomputed folded weights ----------------
// WxP = (Wih0 @ W_in) stored PERMUTED: WxP[f*512 + stage_pos(c)]
// beff = Wih0 @ b_in + bih0 + bhh0 ; bias1 = bih1 + bhh1
__device__ float g_WxP[F_DIM * G_DIM];
__device__ float g_beff[G_DIM];
__device__ float g_bias1[G_DIM];

__global__ void precompute_kernel(const float* __restrict__ Wih0,
                                  const float* __restrict__ W_in,
                                  const float* __restrict__ b_in,
                                  const float* __restrict__ bih0,
                                  const float* __restrict__ bhh0,
                                  const float* __restrict__ bih1,
                                  const float* __restrict__ bhh1) {
    int j = threadIdx.x;  // 0..511 : column of the gate matrices
    float acc[F_DIM];
#pragma unroll
    for (int f = 0; f < F_DIM; f++) acc[f] = 0.0f;
    float bacc = 0.0f;
    for (int k = 0; k < H_DIM; k++) {
        float w = Wih0[j * H_DIM + k];
        bacc += w * b_in[k];
#pragma unroll
        for (int f = 0; f < F_DIM; f++) acc[f] += w * W_in[k * F_DIM + f];
    }
    int pos = stage_pos(j);
#pragma unroll
    for (int f = 0; f < F_DIM; f++) g_WxP[f * G_DIM + pos] = acc[f];
    g_beff[j] = bacc + bih0[j] + bhh0[j];
    g_bias1[j] = bih1[j] + bhh1[j];
}

// ---------------- helpers for the main kernel ----------------
__device__ __forceinline__ void init_acc(const float* __restrict__ sBias, int u0,
                                         ull (&acc)[4][8]) {
#pragma unroll
    for (int g = 0; g < 4; g++) {
        ull b = *(const ull*)(sBias + g * H_DIM + u0);
#pragma unroll
        for (int r = 0; r < 8; r++) acc[g][r] = b;
    }
}

// prefetch one KC=16 chunk of one weight matrix: thread owns column j
__device__ __forceinline__ void ldg_chunk(int m,
                                          const float* __restrict__ Whh0,
                                          const float* __restrict__ Wih1,
                                          const float* __restrict__ Whh1,
                                          int j, float4 (&ra)[4]) {
    const float* src = (m < 8) ? Whh0 : ((m < 16) ? Wih1 : Whh1);
    const float4* p = (const float4*)(src + (size_t)j * H_DIM + (m & 7) * KC);
#pragma unroll
    for (int i = 0; i < 4; i++) ra[i] = p[i];
}

// store chunk into staging buffer in permuted layout: buf[k*512 + pos]
__device__ __forceinline__ void sts_chunk(float* __restrict__ buf, int pos,
                                          const float4 (&ra)[4]) {
#pragma unroll
    for (int i = 0; i < 4; i++) {
        buf[(i * 4 + 0) * G_DIM + pos] = ra[i].x;
        buf[(i * 4 + 1) * G_DIM + pos] = ra[i].y;
        buf[(i * 4 + 2) * G_DIM + pos] = ra[i].z;
        buf[(i * 4 + 3) * G_DIM + pos] = ra[i].w;
    }
}

// Inner GEMM over a KC=16 chunk. Sp -> S[r0][k0] (row stride 128).
// base = hf*128 + lane*4 : this thread's slot within a staged k-row.
__device__ __forceinline__ void gemm16(const float* __restrict__ Sp,
                                       const float* __restrict__ buf,
                                       int base, ull (&acc)[4][8]) {
#pragma unroll
    for (int g2 = 0; g2 < 8; g2++) {          // groups of 2 k
        float2 h2[8];
#pragma unroll
        for (int r = 0; r < 8; r++)
            h2[r] = *(const float2*)(Sp + r * H_DIM + g2 * 2);
#pragma unroll
        for (int kk = 0; kk < 2; kk++) {
            const float* wp = buf + (g2 * 2 + kk) * G_DIM + base;
            ulonglong2 wa = *(const ulonglong2*)(wp);         // gates i,f (2 units each)
            ulonglong2 wb = *(const ulonglong2*)(wp + 256);   // gates g,o
#pragma unroll
            for (int r = 0; r < 8; r++) {
                float hv = kk ? h2[r].y : h2[r].x;
                ull hp = pk2(hv, hv);
                acc[0][r] = fma2(wa.x, hp, acc[0][r]);
                acc[1][r] = fma2(wa.y, hp, acc[1][r]);
                acc[2][r] = fma2(wb.x, hp, acc[2][r]);
                acc[3][r] = fma2(wb.y, hp, acc[3][r]);
            }
        }
    }
}

// x-part GEMM: K=9, permuted weights straight from global (L1/L2 resident, 18KB)
__device__ __forceinline__ void gemm_x(const float* __restrict__ Sp,  // sXs + r0*12
                                       int base, ull (&acc)[4][8]) {
#pragma unroll
    for (int k = 0; k < F_DIM; k++) {
        const float* wp = g_WxP + k * G_DIM + base;
        ulonglong2 wa = *(const ulonglong2*)(wp);
        ulonglong2 wb = *(const ulonglong2*)(wp + 256);
#pragma unroll
        for (int r = 0; r < 8; r++) {
            float hv = Sp[r * 12 + k];
            ull hp = pk2(hv, hv);
            acc[0][r] = fma2(wa.x, hp, acc[0][r]);
            acc[1][r] = fma2(wa.y, hp, acc[1][r]);
            acc[2][r] = fma2(wb.x, hp, acc[2][r]);
            acc[3][r] = fma2(wb.y, hp, acc[3][r]);
        }
    }
}

__device__ __forceinline__ void cell_update(ull (&acc)[4][8],
                                            float* __restrict__ sC,
                                            float* __restrict__ sH,
                                            int r0, int u0) {
#pragma unroll
    for (int r = 0; r < 8; r++) {
        float i0, i1, f0, f1, gg0, gg1, o0, o1;
        unpk2(acc[0][r], i0, i1);
        unpk2(acc[1][r], f0, f1);
        unpk2(acc[2][r], gg0, gg1);
        unpk2(acc[3][r], o0, o1);
        float* cp = sC + (r0 + r) * H_DIM + u0;
        float2 c2 = *(float2*)cp;
        float cn0 = sigf(f0) * c2.x + sigf(i0) * tanhfast(gg0);
        float cn1 = sigf(f1) * c2.y + sigf(i1) * tanhfast(gg1);
        float hn0 = sigf(o0) * tanhfast(cn0);
        float hn1 = sigf(o1) * tanhfast(cn1);
        *(float2*)cp = make_float2(cn0, cn1);
        *(float2*)(sH + (r0 + r) * H_DIM + u0) = make_float2(hn0, hn1);
    }
}

// ---------------- main persistent-tile LSTM kernel ----------------
// grid = 256 CTAs x 512 threads; each CTA owns 64 batch rows for all 128 steps.
// Warp (w): hf = w>>3 (column half), row group rg = w&7 -> rows rg*8..rg*8+7.
// Lane owns units u0 = hf*64 + lane*2 (+1) for all 4 gates. acc = 32 ull.
__global__ void __launch_bounds__(NTH, 1)
lstm_main(const float* __restrict__ x,
          const float* __restrict__ Whh0,
          const float* __restrict__ Wih1,
          const float* __restrict__ Whh1,
          const float* __restrict__ W_out,
          const float* __restrict__ b_out,
          float* __restrict__ out) {
    extern __shared__ float smem[];
    float* sXs    = smem;                  // 64*12  = 768
    float* sH0    = sXs + 768;             // 8192
    float* sH1    = sH0 + 8192;            // 8192
    float* sC0    = sH1 + 8192;            // 8192
    float* sC1    = sC0 + 8192;            // 8192
    float* sW     = sC1 + 8192;            // 2 x 8192 ping-pong (permuted chunks)
    float* sBeff  = sW + 16384;            // 512
    float* sBias1 = sBeff + 512;           // 512

    const int tid  = threadIdx.x;
    const int lane = tid & 31;
    const int warp = tid >> 5;
    const int hf   = warp >> 3;
    const int r0   = (warp & 7) * 8;        // 8 rows per warp
    const int u0   = hf * 64 + lane * 2;    // 2 units per gate per thread
    const int base = hf * 128 + lane * 4;   // slot within staged k-row
    const int b0   = blockIdx.x * TILE_B;
    const int spos = stage_pos(tid);        // where this thread's loaded column lands

    // init states + resident biases
    for (int i = tid; i < 4 * 8192; i += NTH) sH0[i] = 0.0f;   // H0,H1,C0,C1 contiguous
    for (int i = tid; i < G_DIM; i += NTH) { sBeff[i] = g_beff[i]; sBias1[i] = g_bias1[i]; }
    __syncthreads();

    float4 ra[4];
    ldg_chunk(0, Whh0, Wih1, Whh1, tid, ra);   // prefetch chunk 0

    for (int t = 0; t < T_LEN; t++) {
        // x tile for this timestep
        for (int i = tid; i < TILE_B * F_DIM; i += NTH) {
            int r = i / F_DIM, f = i - r * F_DIM;
            sXs[r * 12 + f] = x[(size_t)(b0 + r) * (T_LEN * F_DIM) + t * F_DIM + f];
        }
        __syncthreads();

        // ---- layer 0 ----
        ull acc[4][8];
        init_acc(sBeff, u0, acc);
        gemm_x(&sXs[r0 * 12], base, acc);               // folded x-part, K=9
#pragma unroll 1
        for (int m = 0; m < 8; m++) {                   // Whh0, K=128
            float* buf = sW + (m & 1) * 8192;
            sts_chunk(buf, spos, ra);
            ldg_chunk(m + 1, Whh0, Wih1, Whh1, tid, ra);
            __syncthreads();
            gemm16(&sH0[r0 * H_DIM + m * KC], buf, base, acc);
        }
        __syncthreads();
        cell_update(acc, sC0, sH0, r0, u0);
        __syncthreads();

        // ---- layer 1 ----
        init_acc(sBias1, u0, acc);
#pragma unroll 1
        for (int m = 8; m < 24; m++) {                  // Wih1 (h0-new) then Whh1 (h1-old)
            float* buf = sW + (m & 1) * 8192;
            sts_chunk(buf, spos, ra);
            int mn = (m + 1 == 24) ? 0 : (m + 1);
            ldg_chunk(mn, Whh0, Wih1, Whh1, tid, ra);
            __syncthreads();
            const float* S = (m < 16) ? sH0 : sH1;
            gemm16(&S[r0 * H_DIM + (m & 7) * KC], buf, base, acc);
        }
        __syncthreads();
        cell_update(acc, sC1, sH1, r0, u0);
        __syncthreads();
    }

    // ---- epilogue: logits + softmax on last h1 ----
    if (tid < TILE_B) {
        int r = tid;
        const float* hr = &sH1[r * H_DIM];
        float lg[O_DIM];
#pragma unroll
        for (int o = 0; o < O_DIM; o++) {
            float s = b_out[o];
            for (int k = 0; k < H_DIM; k++) s += hr[k] * W_out[o * H_DIM + k];
            lg[o] = s;
        }
        float m = lg[0];
#pragma unroll
        for (int o = 1; o < O_DIM; o++) m = fmaxf(m, lg[o]);
        float sum = 0.0f;
#pragma unroll
        for (int o = 0; o < O_DIM; o++) { lg[o] = __expf(lg[o] - m); sum += lg[o]; }
        float inv = __fdividef(1.0f, sum);
#pragma unroll
        for (int o = 0; o < O_DIM; o++) out[(size_t)(b0 + r) * O_DIM + o] = lg[o] * inv;
    }
}

// ---------------- launch ----------------
extern "C" void kernel_launch(void* const* d_in, const int* in_sizes, int n_in,
                              void* d_out, int out_size) {
    (void)in_sizes; (void)n_in; (void)out_size;
    const float* x     = (const float*)d_in[0];
    const float* W_in  = (const float*)d_in[1];
    const float* b_in  = (const float*)d_in[2];
    const float* Wih0  = (const float*)d_in[3];
    const float* Whh0  = (const float*)d_in[4];
    const float* bih0  = (const float*)d_in[5];
    const float* bhh0  = (const float*)d_in[6];
    const float* Wih1  = (const float*)d_in[7];
    const float* Whh1  = (const float*)d_in[8];
    const float* bih1  = (const float*)d_in[9];
    const float* bhh1  = (const float*)d_in[10];
    const float* W_out = (const float*)d_in[11];
    const float* b_out = (const float*)d_in[12];
    float* out = (float*)d_out;

    const size_t smem_bytes = (size_t)(768 + 8192 * 6 + 1024) * sizeof(float); // 203776
    cudaFuncSetAttribute(lstm_main, cudaFuncAttributeMaxDynamicSharedMemorySize, (int)smem_bytes);

    precompute_kernel<<<1, G_DIM>>>(Wih0, W_in, b_in, bih0, bhh0, bih1, bhh1);
    lstm_main<<<B_TOT / TILE_B, NTH, smem_bytes>>>(x, Whh0, Wih1, Whh1, W_out, b_out, out);
}

// round 9
// speedup vs baseline: 1.0118x; 1.0011x over previous
#include <cuda_runtime.h>
#include <math.h>

// Problem constants
#define B_TOT  16384
#define T_LEN  128
#define F_DIM  9
#define H_DIM  128
#define O_DIM  12
#define G_DIM  512     // 4*H
#define TILE_B 64
#define NTH    512     // 16 warps: warp owns 8 rows x 256 cols (2 units x 4 gates per lane)
#define KC     16      // k-chunk staged per ping-pong step

typedef unsigned long long ull;

// ---------------- packed f32x2 helpers ----------------
__device__ __forceinline__ ull pk2(float x, float y) {
    ull r;
    asm("mov.b64 %0, {%1, %2};" : "=l"(r) : "f"(x), "f"(y));
    return r;
}
__device__ __forceinline__ void unpk2(ull v, float& lo, float& hi) {
    asm("mov.b64 {%0, %1}, %2;" : "=f"(lo), "=f"(hi) : "l"(v));
}
__device__ __forceinline__ ull fma2(ull a, ull b, ull c) {
    ull d;
    asm("fma.rn.f32x2 %0, %1, %2, %3;" : "=l"(d) : "l"(a), "l"(b), "l"(c));
    return d;
}

// ---------------- pointwise gate math ----------------
__device__ __forceinline__ float sigf(float x) {
    return __fdividef(1.0f, 1.0f + __expf(-x));
}
__device__ __forceinline__ float tanhfast(float x) {
    float xc = fminf(fmaxf(x, -15.0f), 15.0f);
    float e = __expf(2.0f * xc);
    return __fdividef(e - 1.0f, e + 1.0f);
}

// ---------------- staging permutation ----------------
// Column c (0..511) of a gate matrix decomposes as: g = c>>7 (gate), hf = (c>>6)&1,
// l = (c>>1)&31 (lane), u = c&1. Staged position within a 512-float k-row:
//   pos = (g>>1)*256 + hf*128 + l*4 + (g&1)*2 + u
// Reader (warp-half hf, lane l) then finds its 8 weights per k as TWO contiguous
// float4s at offsets  sel*256 + hf*128 + l*4 , sel = 0/1  -> LDS.128 as ulonglong2,
// each ull already the packed f32x2 (unit u0, u0+1) for one gate.
__device__ __forceinline__ int stage_pos(int c) {
    int g = c >> 7, hf = (c >> 6) & 1, l = (c >> 1) & 31, u = c & 1;
    return ((g >> 1) << 8) + (hf << 7) + (l << 2) + ((g & 1) << 1) + u;
}

// ---------------- precomputed folded weights ----------------
// WxP = (Wih0 @ W_in) stored PERMUTED: WxP[f*512 + stage_pos(c)]
// beff = Wih0 @ b_in + bih0 + bhh0 ; bias1 = bih1 + bhh1
__device__ float g_WxP[F_DIM * G_DIM];
__device__ float g_beff[G_DIM];
__device__ float g_bias1[G_DIM];

__global__ void precompute_kernel(const float* __restrict__ Wih0,
                                  const float* __restrict__ W_in,
                                  const float* __restrict__ b_in,
                                  const float* __restrict__ bih0,
                                  const float* __restrict__ bhh0,
                                  const float* __restrict__ bih1,
                                  const float* __restrict__ bhh1) {
    int j = threadIdx.x;  // 0..511 : column of the gate matrices
    float acc[F_DIM];
#pragma unroll
    for (int f = 0; f < F_DIM; f++) acc[f] = 0.0f;
    float bacc = 0.0f;
    for (int k = 0; k < H_DIM; k++) {
        float w = Wih0[j * H_DIM + k];
        bacc += w * b_in[k];
#pragma unroll
        for (int f = 0; f < F_DIM; f++) acc[f] += w * W_in[k * F_DIM + f];
    }
    int pos = stage_pos(j);
#pragma unroll
    for (int f = 0; f < F_DIM; f++) g_WxP[f * G_DIM + pos] = acc[f];
    g_beff[j] = bacc + bih0[j] + bhh0[j];
    g_bias1[j] = bih1[j] + bhh1[j];
}

// ---------------- helpers for the main kernel ----------------
__device__ __forceinline__ void init_acc(const float* __restrict__ sBias, int u0,
                                         ull (&acc)[4][8]) {
#pragma unroll
    for (int g = 0; g < 4; g++) {
        ull b = *(const ull*)(sBias + g * H_DIM + u0);
#pragma unroll
        for (int r = 0; r < 8; r++) acc[g][r] = b;
    }
}

// prefetch one KC=16 chunk of one weight matrix: thread owns column j
__device__ __forceinline__ void ldg_chunk(int m,
                                          const float* __restrict__ Whh0,
                                          const float* __restrict__ Wih1,
                                          const float* __restrict__ Whh1,
                                          int j, float4 (&ra)[4]) {
    const float* src = (m < 8) ? Whh0 : ((m < 16) ? Wih1 : Whh1);
    const float4* p = (const float4*)(src + (size_t)j * H_DIM + (m & 7) * KC);
#pragma unroll
    for (int i = 0; i < 4; i++) ra[i] = p[i];
}

// store chunk into staging buffer in permuted layout: buf[k*512 + pos]
__device__ __forceinline__ void sts_chunk(float* __restrict__ buf, int pos,
                                          const float4 (&ra)[4]) {
#pragma unroll
    for (int i = 0; i < 4; i++) {
        buf[(i * 4 + 0) * G_DIM + pos] = ra[i].x;
        buf[(i * 4 + 1) * G_DIM + pos] = ra[i].y;
        buf[(i * 4 + 2) * G_DIM + pos] = ra[i].z;
        buf[(i * 4 + 3) * G_DIM + pos] = ra[i].w;
    }
}

// Inner GEMM over a KC=16 chunk. Sp -> S[r0][k0] (row stride 128).
// base = hf*128 + lane*4 : this thread's slot within a staged k-row.
__device__ __forceinline__ void gemm16(const float* __restrict__ Sp,
                                       const float* __restrict__ buf,
                                       int base, ull (&acc)[4][8]) {
#pragma unroll
    for (int g2 = 0; g2 < 8; g2++) {          // groups of 2 k
        float2 h2[8];
#pragma unroll
        for (int r = 0; r < 8; r++)
            h2[r] = *(const float2*)(Sp + r * H_DIM + g2 * 2);
#pragma unroll
        for (int kk = 0; kk < 2; kk++) {
            const float* wp = buf + (g2 * 2 + kk) * G_DIM + base;
            ulonglong2 wa = *(const ulonglong2*)(wp);         // gates i,f (2 units each)
            ulonglong2 wb = *(const ulonglong2*)(wp + 256);   // gates g,o
#pragma unroll
            for (int r = 0; r < 8; r++) {
                float hv = kk ? h2[r].y : h2[r].x;
                ull hp = pk2(hv, hv);
                acc[0][r] = fma2(wa.x, hp, acc[0][r]);
                acc[1][r] = fma2(wa.y, hp, acc[1][r]);
                acc[2][r] = fma2(wb.x, hp, acc[2][r]);
                acc[3][r] = fma2(wb.y, hp, acc[3][r]);
            }
        }
    }
}

// x-part GEMM: K=9, permuted weights straight from global (L1/L2 resident, 18KB)
__device__ __forceinline__ void gemm_x(const float* __restrict__ Sp,  // sXs + r0*12
                                       int base, ull (&acc)[4][8]) {
#pragma unroll
    for (int k = 0; k < F_DIM; k++) {
        const float* wp = g_WxP + k * G_DIM + base;
        ulonglong2 wa = *(const ulonglong2*)(wp);
        ulonglong2 wb = *(const ulonglong2*)(wp + 256);
#pragma unroll
        for (int r = 0; r < 8; r++) {
            float hv = Sp[r * 12 + k];
            ull hp = pk2(hv, hv);
            acc[0][r] = fma2(wa.x, hp, acc[0][r]);
            acc[1][r] = fma2(wa.y, hp, acc[1][r]);
            acc[2][r] = fma2(wb.x, hp, acc[2][r]);
            acc[3][r] = fma2(wb.y, hp, acc[3][r]);
        }
    }
}

__device__ __forceinline__ void cell_update(ull (&acc)[4][8],
                                            float* __restrict__ sC,
                                            float* __restrict__ sH,
                                            int r0, int u0) {
#pragma unroll
    for (int r = 0; r < 8; r++) {
        float i0, i1, f0, f1, gg0, gg1, o0, o1;
        unpk2(acc[0][r], i0, i1);
        unpk2(acc[1][r], f0, f1);
        unpk2(acc[2][r], gg0, gg1);
        unpk2(acc[3][r], o0, o1);
        float* cp = sC + (r0 + r) * H_DIM + u0;
        float2 c2 = *(float2*)cp;
        float cn0 = sigf(f0) * c2.x + sigf(i0) * tanhfast(gg0);
        float cn1 = sigf(f1) * c2.y + sigf(i1) * tanhfast(gg1);
        float hn0 = sigf(o0) * tanhfast(cn0);
        float hn1 = sigf(o1) * tanhfast(cn1);
        *(float2*)cp = make_float2(cn0, cn1);
        *(float2*)(sH + (r0 + r) * H_DIM + u0) = make_float2(hn0, hn1);
    }
}

// ---------------- main persistent-tile LSTM kernel ----------------
// grid = 256 CTAs x 512 threads; each CTA owns 64 batch rows for all 128 steps.
// Warp (w): hf = w>>3 (column half), row group rg = w&7 -> rows rg*8..rg*8+7.
// Lane owns units u0 = hf*64 + lane*2 (+1) for all 4 gates. acc = 32 ull.
__global__ void __launch_bounds__(NTH, 1)
lstm_main(const float* __restrict__ x,
          const float* __restrict__ Whh0,
          const float* __restrict__ Wih1,
          const float* __restrict__ Whh1,
          const float* __restrict__ W_out,
          const float* __restrict__ b_out,
          float* __restrict__ out) {
    extern __shared__ float smem[];
    float* sXs    = smem;                  // 64*12  = 768
    float* sH0    = sXs + 768;             // 8192
    float* sH1    = sH0 + 8192;            // 8192
    float* sC0    = sH1 + 8192;            // 8192
    float* sC1    = sC0 + 8192;            // 8192
    float* sW     = sC1 + 8192;            // 2 x 8192 ping-pong (permuted chunks)
    float* sBeff  = sW + 16384;            // 512
    float* sBias1 = sBeff + 512;           // 512

    const int tid  = threadIdx.x;
    const int lane = tid & 31;
    const int warp = tid >> 5;
    const int hf   = warp >> 3;
    const int r0   = (warp & 7) * 8;        // 8 rows per warp
    const int u0   = hf * 64 + lane * 2;    // 2 units per gate per thread
    const int base = hf * 128 + lane * 4;   // slot within staged k-row
    const int b0   = blockIdx.x * TILE_B;
    const int spos = stage_pos(tid);        // where this thread's loaded column lands

    // init states + resident biases
    for (int i = tid; i < 4 * 8192; i += NTH) sH0[i] = 0.0f;   // H0,H1,C0,C1 contiguous
    for (int i = tid; i < G_DIM; i += NTH) { sBeff[i] = g_beff[i]; sBias1[i] = g_bias1[i]; }
    __syncthreads();

    float4 ra[4];
    ldg_chunk(0, Whh0, Wih1, Whh1, tid, ra);   // prefetch chunk 0

    for (int t = 0; t < T_LEN; t++) {
        // x tile for this timestep
        for (int i = tid; i < TILE_B * F_DIM; i += NTH) {
            int r = i / F_DIM, f = i - r * F_DIM;
            sXs[r * 12 + f] = x[(size_t)(b0 + r) * (T_LEN * F_DIM) + t * F_DIM + f];
        }
        __syncthreads();

        // ---- layer 0 ----
        ull acc[4][8];
        init_acc(sBeff, u0, acc);
        gemm_x(&sXs[r0 * 12], base, acc);               // folded x-part, K=9
#pragma unroll 1
        for (int m = 0; m < 8; m++) {                   // Whh0, K=128
            float* buf = sW + (m & 1) * 8192;
            sts_chunk(buf, spos, ra);
            ldg_chunk(m + 1, Whh0, Wih1, Whh1, tid, ra);
            __syncthreads();
            gemm16(&sH0[r0 * H_DIM + m * KC], buf, base, acc);
        }
        __syncthreads();
        cell_update(acc, sC0, sH0, r0, u0);
        __syncthreads();

        // ---- layer 1 ----
        init_acc(sBias1, u0, acc);
#pragma unroll 1
        for (int m = 8; m < 24; m++) {                  // Wih1 (h0-new) then Whh1 (h1-old)
            float* buf = sW + (m & 1) * 8192;
            sts_chunk(buf, spos, ra);
            int mn = (m + 1 == 24) ? 0 : (m + 1);
            ldg_chunk(mn, Whh0, Wih1, Whh1, tid, ra);
            __syncthreads();
            const float* S = (m < 16) ? sH0 : sH1;
            gemm16(&S[r0 * H_DIM + (m & 7) * KC], buf, base, acc);
        }
        __syncthreads();
        cell_update(acc, sC1, sH1, r0, u0);
        __syncthreads();
    }

    // ---- epilogue: logits + softmax on last h1 ----
    if (tid < TILE_B) {
        int r = tid;
        const float* hr = &sH1[r * H_DIM];
        float lg[O_DIM];
#pragma unroll
        for (int o = 0; o < O_DIM; o++) {
            float s = b_out[o];
            for (int k = 0; k < H_DIM; k++) s += hr[k] * W_out[o * H_DIM + k];
            lg[o] = s;
        }
        float m = lg[0];
#pragma unroll
        for (int o = 1; o < O_DIM; o++) m = fmaxf(m, lg[o]);
        float sum = 0.0f;
#pragma unroll
        for (int o = 0; o < O_DIM; o++) { lg[o] = __expf(lg[o] - m); sum += lg[o]; }
        float inv = __fdividef(1.0f, sum);
#pragma unroll
        for (int o = 0; o < O_DIM; o++) out[(size_t)(b0 + r) * O_DIM + o] = lg[o] * inv;
    }
}

// ---------------- launch ----------------
extern "C" void kernel_launch(void* const* d_in, const int* in_sizes, int n_in,
                              void* d_out, int out_size) {
    (void)in_sizes; (void)n_in; (void)out_size;
    const float* x     = (const float*)d_in[0];
    const float* W_in  = (const float*)d_in[1];
    const float* b_in  = (const float*)d_in[2];
    const float* Wih0  = (const float*)d_in[3];
    const float* Whh0  = (const float*)d_in[4];
    const float* bih0  = (const float*)d_in[5];
    const float* bhh0  = (const float*)d_in[6];
    const float* Wih1  = (const float*)d_in[7];
    const float* Whh1  = (const float*)d_in[8];
    const float* bih1  = (const float*)d_in[9];
    const float* bhh1  = (const float*)d_in[10];
    const float* W_out = (const float*)d_in[11];
    const float* b_out = (const float*)d_in[12];
    float* out = (float*)d_out;

    const size_t smem_bytes = (size_t)(768 + 8192 * 6 + 1024) * sizeof(float); // 203776
    cudaFuncSetAttribute(lstm_main, cudaFuncAttributeMaxDynamicSharedMemorySize, (int)smem_bytes);

    precompute_kernel<<<1, G_DIM>>>(Wih0, W_in, b_in, bih0, bhh0, bih1, bhh1);
    lstm_main<<<B_TOT / TILE_B, NTH, smem_bytes>>>(x, Whh0, Wih1, Whh1, W_out, b_out, out);
}